// round 15
// baseline (speedup 1.0000x reference)
#include <cuda_runtime.h>
#include <cstdint>

// ============================================================================
// Binary conv1d (sign x sign) + maxpool(7,2) + per-channel threshold.
// FP8 e4m3 mma.sync.m16n8k32; A fragments in L1-resident global (g_Apack).
// This round: 4 CTAs/SM (32 warps) -- regs capped to 64 (pf split 2+2+1),
// OUT single-buffered (+1 mid-tile sync) so smem = 31.9KB/CTA and Apack
// stays L1-resident. Tests whether the ~525us legacy-mma cap has slack.
// ============================================================================

#define BATCH 64
#define CIN 64
#define LEN 16384
#define COUT 128
#define LOUT 8189
#define TILE_OUT 29
#define TILES_PER_B 283
#define TOTAL_TILES (BATCH * TILES_PER_B)   // 18112
#define NTHREADS 256
#define GRID 592                             // 4 CTAs per SM

#define X_PITCH 96             // permuted row: LDS.64 conflict-free
#define OUT_PITCH 36

// dynamic smem layout
#define SM_OUT  0                                   // float OUT[128*36] = 18432
#define SM_X    (COUT * OUT_PITCH * 4)              // uchar X[2][70*96] = 13440
#define SMEM_BYTES (SM_X + 2 * 70 * X_PITCH)        // 31872 B

#define FP8_P1 0x38u

#define MMA_F8(d, a, b0_, b1_)                                                 \
    asm volatile(                                                              \
        "mma.sync.aligned.m16n8k32.row.col.f32.e4m3.e4m3.f32 "                 \
        "{%0,%1,%2,%3},{%4,%5,%6,%7},{%8,%9},{%0,%1,%2,%3};"                   \
        : "+f"((d)[0]), "+f"((d)[1]), "+f"((d)[2]), "+f"((d)[3])               \
        : "r"((a)[0]), "r"((a)[1]), "r"((a)[2]), "r"((a)[3]),                  \
          "r"(b0_), "r"(b1_))

// pre-packed A fragments: [wid][s][lane] -> uint4 (coalesced per warp-step)
__device__ uint4 g_Apack[8 * 14 * 32];

__global__ void pack_A_kernel(const float* __restrict__ W) {
    const int s    = blockIdx.x;           // 0..13
    const int tid  = threadIdx.x;
    const int wid  = tid >> 5;
    const int lane = tid & 31;
    const int gr   = lane >> 2;
    const int tg   = lane & 3;
    uint32_t r[4];
    #pragma unroll
    for (int j = 0; j < 4; j++) {
        const int row = wid * 16 + gr + (j & 1) * 8;
        const int kap = 32 * s + (j >> 1) * 16 + tg * 4;
        uint32_t v = 0;
        #pragma unroll
        for (int i = 0; i < 4; i++) {
            const int kk = kap + i;
            const float w = W[row * 448 + (kk & 63) * 7 + (kk >> 6)];
            v |= (FP8_P1 | ((w < 0.f) ? 0x80u : 0u)) << (8 * i);
        }
        r[j] = v;
    }
    g_Apack[(wid * 14 + s) * 32 + lane] = make_uint4(r[0], r[1], r[2], r[3]);
}

__global__ void __launch_bounds__(NTHREADS, 4)
binconv_kernel(const float* __restrict__ I,
               const float* __restrict__ TP, const float* __restrict__ TMi,
               const float* __restrict__ PS, const float* __restrict__ MS,
               float* __restrict__ out)
{
    extern __shared__ char smem[];
    float*         OUT = (float*)(smem + SM_OUT);        // [COUT*OUT_PITCH]
    unsigned char* X   = (unsigned char*)(smem + SM_X);  // [2][70*X_PITCH]

    const int tid  = threadIdx.x;
    const int lane = tid & 31;
    const int wid  = tid >> 5;
    const int gr   = lane >> 2;
    const int tg   = lane & 3;

    const int r0 = wid * 16 + gr;
    const int r1 = r0 + 8;

    const uint4* __restrict__ Ap = g_Apack + wid * 14 * 32 + lane;

    // ---- prefetch registers: 2 items x 4 floats live at once ----
    float pf[2][4];

    // load one item (idx) into pf[slot]
    auto pf1 = [&](int slot, int b, int P0, int idx) {
        const int ci4 = idx / 70;
        const int p   = idx - ci4 * 70;
        const int gl  = P0 - 3 + p;
        const bool inb = (gl >= 0) && (gl < LEN);
        const float* ip = I + (size_t)b * (size_t)CIN * LEN
                        + (size_t)(ci4 * 4) * LEN + gl;
        pf[slot][0] = inb ? __ldcs(ip)           : -1.f;
        pf[slot][1] = inb ? __ldcs(ip + LEN)     : -1.f;
        pf[slot][2] = inb ? __ldcs(ip + 2 * LEN) : -1.f;
        pf[slot][3] = inb ? __ldcs(ip + 3 * LEN) : -1.f;
    };

    auto cv1 = [&](unsigned char* Xb, int idx, const float* v) {
        const int ci4 = idx / 70;
        const int p   = idx - ci4 * 70;
        const uint32_t u0 = __float_as_uint(v[0]);
        const uint32_t u1 = __float_as_uint(v[1]);
        const uint32_t u2 = __float_as_uint(v[2]);
        const uint32_t u3 = __float_as_uint(v[3]);
        const uint32_t t  = __byte_perm(u0, u1, 0x0073);
        const uint32_t s2 = __byte_perm(u2, u3, 0x7300);
        const uint32_t r  = __byte_perm(t, s2, 0x7610);
        const uint32_t pk = (r & 0x80808080u) | 0x38383838u;
        const int h  = ci4 >> 3;
        const int w  = ci4 & 7;
        const int wp = ((w & 3) << 1) + (w >> 2);
        *(uint32_t*)&Xb[p * X_PITCH + h * 32 + wp * 4] = pk;
    };

    unsigned g = (unsigned)blockIdx.x;
    int b  = (int)(g / TILES_PER_B);
    int jt = (int)g - b * TILES_PER_B;

    int xb = 0;
    int prev_valid = 0, b_prev = 0, t0_prev = 0, nt_prev = 0;

    if (g < TOTAL_TILES) {
        const int P0 = jt * (TILE_OUT * 2);
        unsigned char* Xb = X;
        pf1(0, b, P0, tid); pf1(1, b, P0, tid + 256);
        cv1(Xb, tid, pf[0]); cv1(Xb, tid + 256, pf[1]);
        pf1(0, b, P0, tid + 512);
        if (tid + 1024 < 1120) pf1(1, b, P0, tid + 1024);
        cv1(Xb, tid + 512, pf[0]);
        if (tid + 1024 < 1120) cv1(Xb, tid + 1024, pf[1]);
        pf1(0, b, P0, tid + 768);
        cv1(Xb, tid + 768, pf[0]);
    }
    __syncthreads();

    while (g < TOTAL_TILES) {
        const int t0 = jt * TILE_OUT;
        const int nt = min(TILE_OUT, LOUT - t0);
        const int b_cur = b;

        int bn = b, jn = jt + GRID;
        while (jn >= TILES_PER_B) { jn -= TILES_PER_B; bn++; }
        const unsigned gn = g + GRID;
        const int Pn = jn * (TILE_OUT * 2);
        const bool more = (gn < TOTAL_TILES);

        // chunk A loads (items 0,1)
        if (more) { pf1(0, bn, Pn, tid); pf1(1, bn, Pn, tid + 256); }

        float acc[8][4];
        #pragma unroll
        for (int n8 = 0; n8 < 8; n8++)
            #pragma unroll
            for (int r = 0; r < 4; r++) acc[n8][r] = 0.f;

        const unsigned char* Xc = X + xb * (70 * X_PITCH);
        unsigned char* Xn = X + (xb ^ 1) * (70 * X_PITCH);

        // ---- MMA pairs k = 0..2 ----
        #pragma unroll
        for (int k = 0; k < 3; k++) {
            const uint4 a0 = Ap[(2 * k) * 32];
            const uint4 a1 = Ap[(2 * k + 1) * 32];
            #pragma unroll
            for (int n8 = 0; n8 < 8; n8++) {
                const int prel = n8 * 8 + gr + k;
                const uint2 b0 = *(const uint2*)&Xc[prel * X_PITCH + tg * 8];
                const uint2 b1 = *(const uint2*)&Xc[prel * X_PITCH + 32 + tg * 8];
                MMA_F8(acc[n8], ((const uint32_t*)&a0), b0.x, b0.y);
                MMA_F8(acc[n8], ((const uint32_t*)&a1), b1.x, b1.y);
            }
        }

        // ---- store previous tile's output (reads OUT) ----
        if (prev_valid && lane < nt_prev) {
            #pragma unroll
            for (int it = 0; it < 16; it++) {
                const int row = wid + it * 8;
                out[((size_t)b_prev * COUT + row) * LOUT + t0_prev + lane] =
                    OUT[row * OUT_PITCH + lane];
            }
        }
        __syncthreads();   // OUT reads (tile g-1) done before pool rewrites

        // ---- MMA pairs k = 3..4 ----
        #pragma unroll
        for (int k = 3; k < 5; k++) {
            const uint4 a0 = Ap[(2 * k) * 32];
            const uint4 a1 = Ap[(2 * k + 1) * 32];
            #pragma unroll
            for (int n8 = 0; n8 < 8; n8++) {
                const int prel = n8 * 8 + gr + k;
                const uint2 b0 = *(const uint2*)&Xc[prel * X_PITCH + tg * 8];
                const uint2 b1 = *(const uint2*)&Xc[prel * X_PITCH + 32 + tg * 8];
                MMA_F8(acc[n8], ((const uint32_t*)&a0), b0.x, b0.y);
                MMA_F8(acc[n8], ((const uint32_t*)&a1), b1.x, b1.y);
            }
        }

        // convert items 0,1; load items 2,3 (tensor shadow)
        if (more) {
            cv1(Xn, tid, pf[0]); cv1(Xn, tid + 256, pf[1]);
            pf1(0, bn, Pn, tid + 512);
            if (tid + 1024 < 1120) pf1(1, bn, Pn, tid + 1024);
        }

        // ---- MMA pairs k = 5..6 ----
        #pragma unroll
        for (int k = 5; k < 7; k++) {
            const uint4 a0 = Ap[(2 * k) * 32];
            const uint4 a1 = Ap[(2 * k + 1) * 32];
            #pragma unroll
            for (int n8 = 0; n8 < 8; n8++) {
                const int prel = n8 * 8 + gr + k;
                const uint2 b0 = *(const uint2*)&Xc[prel * X_PITCH + tg * 8];
                const uint2 b1 = *(const uint2*)&Xc[prel * X_PITCH + 32 + tg * 8];
                MMA_F8(acc[n8], ((const uint32_t*)&a0), b0.x, b0.y);
                MMA_F8(acc[n8], ((const uint32_t*)&a1), b1.x, b1.y);
            }
        }

        // convert items 2,3; load+convert item 4
        if (more) {
            cv1(Xn, tid + 512, pf[0]);
            if (tid + 1024 < 1120) cv1(Xn, tid + 1024, pf[1]);
            pf1(0, bn, Pn, tid + 768);
            cv1(Xn, tid + 768, pf[0]);
        }

        // ---- pool(7,2) + threshold (rolling shuffles) -> OUT ----
        #pragma unroll
        for (int row = 0; row < 2; row++) {
            float ev[8], q[8];
            #pragma unroll
            for (int n8 = 0; n8 < 8; n8++) {
                ev[n8] = acc[n8][row * 2];
                q[n8]  = fmaxf(acc[n8][row * 2], acc[n8][row * 2 + 1]);
            }
            const int rr = row ? r1 : r0;
            const float rtp = TP[rr], rtm = TMi[rr];
            const float rps = PS[rr], rms = MS[rr];

            float s1n = __shfl_sync(0xFFFFFFFFu, q[0],  (tg + 1) & 3, 4);
            float s2n = __shfl_sync(0xFFFFFFFFu, q[0],  (tg + 2) & 3, 4);
            float sen = __shfl_sync(0xFFFFFFFFu, ev[0], (tg + 3) & 3, 4);
            #pragma unroll
            for (int n8 = 0; n8 < 8; n8++) {
                const float s1c = s1n, s2c = s2n, sec = sen;
                const int nn = (n8 < 7) ? n8 + 1 : 7;
                s1n = __shfl_sync(0xFFFFFFFFu, q[nn],  (tg + 1) & 3, 4);
                s2n = __shfl_sync(0xFFFFFFFFu, q[nn],  (tg + 2) & 3, 4);
                sen = __shfl_sync(0xFFFFFFFFu, ev[nn], (tg + 3) & 3, 4);
                const int jo = 4 * n8 + tg;
                if (jo < TILE_OUT) {
                    const float v1 = (tg < 3) ? s1c : s1n;
                    const float v2 = (tg < 2) ? s2c : s2n;
                    const float e  = (tg < 1) ? sec : sen;
                    const float mx = fmaxf(fmaxf(q[n8], v1), fmaxf(v2, e));
                    const float pos = (mx > rtp) ? rps : -rps;
                    const float neg = (mx > rtm) ? rms : -rms;
                    OUT[rr * OUT_PITCH + jo] = (mx >= 0.f) ? pos : neg;
                }
            }
        }

        __syncthreads();   // OUT(g) + X[xb^1] visible; X[xb] free

        prev_valid = 1; b_prev = b_cur; t0_prev = t0; nt_prev = nt;
        xb ^= 1;
        b = bn; jt = jn;
        g = gn;
    }

    // ---- drain: store the last tile ----
    if (prev_valid && lane < nt_prev) {
        #pragma unroll
        for (int it = 0; it < 16; it++) {
            const int row = wid + it * 8;
            out[((size_t)b_prev * COUT + row) * LOUT + t0_prev + lane] =
                OUT[row * OUT_PITCH + lane];
        }
    }
}

extern "C" void kernel_launch(void* const* d_in, const int* in_sizes, int n_in,
                              void* d_out, int out_size) {
    const float* I  = (const float*)d_in[0];
    const float* W  = (const float*)d_in[1];
    const float* tp = (const float*)d_in[2];
    const float* tm = (const float*)d_in[3];
    const float* ps = (const float*)d_in[4];
    const float* ms = (const float*)d_in[5];
    float* out = (float*)d_out;

    cudaFuncSetAttribute(binconv_kernel,
                         cudaFuncAttributeMaxDynamicSharedMemorySize, SMEM_BYTES);

    pack_A_kernel<<<14, NTHREADS>>>(W);
    binconv_kernel<<<GRID, NTHREADS, SMEM_BYTES>>>(I, tp, tm, ps, ms, out);
}

// round 16
// speedup vs baseline: 1.4202x; 1.4202x over previous
#include <cuda_runtime.h>
#include <cstdint>

// ============================================================================
// Binary conv1d (sign x sign) + maxpool(7,2) + per-channel threshold.
// FINAL (revert to R14 optimum): FP8 e4m3 mma.sync.m16n8k32; A fragments in
// L1-resident global (g_Apack, packed by a parallel 14-block kernel);
// 3 CTAs/SM (regs=80); cross-tile register prefetch + convert/store threaded
// into the MMA stream; X & OUT double-buffered; one __syncthreads per tile.
// Main kernel runs at ~99% of the sm_103 legacy-mma MAC dispatch floor
// (~512 MACs/cyc/SM -> ~519us predicted, 525us measured).
// R15 (4 CTAs/SM) regressed to 753us via L1 capacity collapse -- reverted.
// ============================================================================

#define BATCH 64
#define CIN 64
#define LEN 16384
#define COUT 128
#define LOUT 8189
#define TILE_OUT 29
#define TILES_PER_B 283
#define TOTAL_TILES (BATCH * TILES_PER_B)   // 18112
#define NTHREADS 256
#define GRID 444                             // 3 CTAs per SM

#define X_PITCH 96             // permuted row: LDS.64 conflict-free
#define OUT_PITCH 36

// dynamic smem layout
#define SM_OUT  0                                   // float OUT[2][128*36]
#define SM_X    (2 * COUT * OUT_PITCH * 4)          // uchar X[2][70*96]
#define SMEM_BYTES (SM_X + 2 * 70 * X_PITCH)        // 50304 B

#define FP8_P1 0x38u

#define MMA_F8(d, a, b0_, b1_)                                                 \
    asm volatile(                                                              \
        "mma.sync.aligned.m16n8k32.row.col.f32.e4m3.e4m3.f32 "                 \
        "{%0,%1,%2,%3},{%4,%5,%6,%7},{%8,%9},{%0,%1,%2,%3};"                   \
        : "+f"((d)[0]), "+f"((d)[1]), "+f"((d)[2]), "+f"((d)[3])               \
        : "r"((a)[0]), "r"((a)[1]), "r"((a)[2]), "r"((a)[3]),                  \
          "r"(b0_), "r"(b1_))

// pre-packed A fragments: [wid][s][lane] -> uint4 (coalesced per warp-step)
__device__ uint4 g_Apack[8 * 14 * 32];

// parallel pack: block = k-step (14), thread = (wid, lane)
__global__ void pack_A_kernel(const float* __restrict__ W) {
    const int s    = blockIdx.x;           // 0..13
    const int tid  = threadIdx.x;
    const int wid  = tid >> 5;
    const int lane = tid & 31;
    const int gr   = lane >> 2;
    const int tg   = lane & 3;
    uint32_t r[4];
    #pragma unroll
    for (int j = 0; j < 4; j++) {
        const int row = wid * 16 + gr + (j & 1) * 8;
        const int kap = 32 * s + (j >> 1) * 16 + tg * 4;
        uint32_t v = 0;
        #pragma unroll
        for (int i = 0; i < 4; i++) {
            const int kk = kap + i;
            const float w = W[row * 448 + (kk & 63) * 7 + (kk >> 6)];
            v |= (FP8_P1 | ((w < 0.f) ? 0x80u : 0u)) << (8 * i);
        }
        r[j] = v;
    }
    g_Apack[(wid * 14 + s) * 32 + lane] = make_uint4(r[0], r[1], r[2], r[3]);
}

__global__ void __launch_bounds__(NTHREADS, 3)
binconv_kernel(const float* __restrict__ I,
               const float* __restrict__ TP, const float* __restrict__ TMi,
               const float* __restrict__ PS, const float* __restrict__ MS,
               float* __restrict__ out)
{
    extern __shared__ char smem[];
    float*         OUT = (float*)(smem + SM_OUT);        // [2][COUT*OUT_PITCH]
    unsigned char* X   = (unsigned char*)(smem + SM_X);  // [2][70*X_PITCH]

    const int tid  = threadIdx.x;
    const int lane = tid & 31;
    const int wid  = tid >> 5;
    const int gr   = lane >> 2;
    const int tg   = lane & 3;

    const int r0 = wid * 16 + gr;
    const int r1 = r0 + 8;

    const uint4* __restrict__ Ap = g_Apack + wid * 14 * 32 + lane;

    // ---- prefetch registers: up to 3 items x 4 floats live at once ----
    float pf[3][4];

    auto prefetchA = [&](int b, int P0) {
        const float* Ib = I + (size_t)b * (size_t)CIN * LEN;
        #pragma unroll
        for (int it = 0; it < 3; it++) {
            const int idx = tid + it * NTHREADS;
            const int ci4 = idx / 70;
            const int p   = idx - ci4 * 70;
            const int gl  = P0 - 3 + p;
            const bool inb = (gl >= 0) && (gl < LEN);
            const float* ip = Ib + (size_t)(ci4 * 4) * LEN + gl;
            pf[it][0] = inb ? __ldcs(ip)           : -1.f;
            pf[it][1] = inb ? __ldcs(ip + LEN)     : -1.f;
            pf[it][2] = inb ? __ldcs(ip + 2 * LEN) : -1.f;
            pf[it][3] = inb ? __ldcs(ip + 3 * LEN) : -1.f;
        }
    };
    auto prefetchB = [&](int b, int P0) {
        const float* Ib = I + (size_t)b * (size_t)CIN * LEN;
        #pragma unroll
        for (int it = 0; it < 2; it++) {
            const int idx = tid + (it + 3) * NTHREADS;
            if (idx < 16 * 70) {
                const int ci4 = idx / 70;
                const int p   = idx - ci4 * 70;
                const int gl  = P0 - 3 + p;
                const bool inb = (gl >= 0) && (gl < LEN);
                const float* ip = Ib + (size_t)(ci4 * 4) * LEN + gl;
                pf[it][0] = inb ? __ldcs(ip)           : -1.f;
                pf[it][1] = inb ? __ldcs(ip + LEN)     : -1.f;
                pf[it][2] = inb ? __ldcs(ip + 2 * LEN) : -1.f;
                pf[it][3] = inb ? __ldcs(ip + 3 * LEN) : -1.f;
            }
        }
    };

    auto cv1 = [&](unsigned char* Xb, int idx, const float* v) {
        const int ci4 = idx / 70;
        const int p   = idx - ci4 * 70;
        const uint32_t u0 = __float_as_uint(v[0]);
        const uint32_t u1 = __float_as_uint(v[1]);
        const uint32_t u2 = __float_as_uint(v[2]);
        const uint32_t u3 = __float_as_uint(v[3]);
        const uint32_t t  = __byte_perm(u0, u1, 0x0073);
        const uint32_t s2 = __byte_perm(u2, u3, 0x7300);
        const uint32_t r  = __byte_perm(t, s2, 0x7610);
        const uint32_t pk = (r & 0x80808080u) | 0x38383838u;
        const int h  = ci4 >> 3;
        const int w  = ci4 & 7;
        const int wp = ((w & 3) << 1) + (w >> 2);
        *(uint32_t*)&Xb[p * X_PITCH + h * 32 + wp * 4] = pk;
    };
    auto convertA = [&](int xb) {
        unsigned char* Xb = X + xb * (70 * X_PITCH);
        #pragma unroll
        for (int it = 0; it < 3; it++) cv1(Xb, tid + it * NTHREADS, pf[it]);
    };
    auto convertB = [&](int xb) {
        unsigned char* Xb = X + xb * (70 * X_PITCH);
        #pragma unroll
        for (int it = 0; it < 2; it++) {
            const int idx = tid + (it + 3) * NTHREADS;
            if (idx < 16 * 70) cv1(Xb, idx, pf[it]);
        }
    };

    unsigned g = (unsigned)blockIdx.x;
    int b  = (int)(g / TILES_PER_B);
    int jt = (int)g - b * TILES_PER_B;

    int xb = 0, ob = 0;
    int prev_valid = 0, b_prev = 0, t0_prev = 0, nt_prev = 0;

    if (g < TOTAL_TILES) {
        prefetchA(b, jt * (TILE_OUT * 2));
        convertA(0);
        prefetchB(b, jt * (TILE_OUT * 2));
        convertB(0);
    }
    __syncthreads();

    while (g < TOTAL_TILES) {
        const int t0 = jt * TILE_OUT;
        const int nt = min(TILE_OUT, LOUT - t0);
        const int b_cur = b;

        int bn = b, jn = jt + GRID;
        while (jn >= TILES_PER_B) { jn -= TILES_PER_B; bn++; }
        const unsigned gn = g + GRID;
        const int Pn = jn * (TILE_OUT * 2);

        if (gn < TOTAL_TILES) prefetchA(bn, Pn);

        float acc[8][4];
        #pragma unroll
        for (int n8 = 0; n8 < 8; n8++)
            #pragma unroll
            for (int r = 0; r < 4; r++) acc[n8][r] = 0.f;

        const unsigned char* Xc = X + xb * (70 * X_PITCH);

        // ---- MMA pairs k = 0..2 (A from L1-resident global) ----
        #pragma unroll
        for (int k = 0; k < 3; k++) {
            const uint4 a0 = Ap[(2 * k) * 32];
            const uint4 a1 = Ap[(2 * k + 1) * 32];
            #pragma unroll
            for (int n8 = 0; n8 < 8; n8++) {
                const int prel = n8 * 8 + gr + k;
                const uint2 b0 = *(const uint2*)&Xc[prel * X_PITCH + tg * 8];
                const uint2 b1 = *(const uint2*)&Xc[prel * X_PITCH + 32 + tg * 8];
                MMA_F8(acc[n8], ((const uint32_t*)&a0), b0.x, b0.y);
                MMA_F8(acc[n8], ((const uint32_t*)&a1), b1.x, b1.y);
            }
        }

        // ---- store previous tile's output (tensor shadow) ----
        if (prev_valid && lane < nt_prev) {
            const float* op = OUT + (ob ^ 1) * (COUT * OUT_PITCH);
            #pragma unroll
            for (int it = 0; it < 16; it++) {
                const int row = wid + it * 8;
                out[((size_t)b_prev * COUT + row) * LOUT + t0_prev + lane] =
                    op[row * OUT_PITCH + lane];
            }
        }

        // ---- MMA pairs k = 3..4 ----
        #pragma unroll
        for (int k = 3; k < 5; k++) {
            const uint4 a0 = Ap[(2 * k) * 32];
            const uint4 a1 = Ap[(2 * k + 1) * 32];
            #pragma unroll
            for (int n8 = 0; n8 < 8; n8++) {
                const int prel = n8 * 8 + gr + k;
                const uint2 b0 = *(const uint2*)&Xc[prel * X_PITCH + tg * 8];
                const uint2 b1 = *(const uint2*)&Xc[prel * X_PITCH + 32 + tg * 8];
                MMA_F8(acc[n8], ((const uint32_t*)&a0), b0.x, b0.y);
                MMA_F8(acc[n8], ((const uint32_t*)&a1), b1.x, b1.y);
            }
        }

        // ---- convert half A, then issue half B loads (tensor shadow) ----
        if (gn < TOTAL_TILES) { convertA(xb ^ 1); prefetchB(bn, Pn); }

        // ---- MMA pairs k = 5..6 ----
        #pragma unroll
        for (int k = 5; k < 7; k++) {
            const uint4 a0 = Ap[(2 * k) * 32];
            const uint4 a1 = Ap[(2 * k + 1) * 32];
            #pragma unroll
            for (int n8 = 0; n8 < 8; n8++) {
                const int prel = n8 * 8 + gr + k;
                const uint2 b0 = *(const uint2*)&Xc[prel * X_PITCH + tg * 8];
                const uint2 b1 = *(const uint2*)&Xc[prel * X_PITCH + 32 + tg * 8];
                MMA_F8(acc[n8], ((const uint32_t*)&a0), b0.x, b0.y);
                MMA_F8(acc[n8], ((const uint32_t*)&a1), b1.x, b1.y);
            }
        }

        if (gn < TOTAL_TILES) convertB(xb ^ 1);

        // ---- pool(7,2) + threshold (rolling shuffles) ----
        #pragma unroll
        for (int row = 0; row < 2; row++) {
            float ev[8], q[8];
            #pragma unroll
            for (int n8 = 0; n8 < 8; n8++) {
                ev[n8] = acc[n8][row * 2];
                q[n8]  = fmaxf(acc[n8][row * 2], acc[n8][row * 2 + 1]);
            }
            const int rr = row ? r1 : r0;
            const float rtp = TP[rr], rtm = TMi[rr];
            const float rps = PS[rr], rms = MS[rr];
            float* outp = OUT + ob * (COUT * OUT_PITCH);

            float s1n = __shfl_sync(0xFFFFFFFFu, q[0],  (tg + 1) & 3, 4);
            float s2n = __shfl_sync(0xFFFFFFFFu, q[0],  (tg + 2) & 3, 4);
            float sen = __shfl_sync(0xFFFFFFFFu, ev[0], (tg + 3) & 3, 4);
            #pragma unroll
            for (int n8 = 0; n8 < 8; n8++) {
                const float s1c = s1n, s2c = s2n, sec = sen;
                const int nn = (n8 < 7) ? n8 + 1 : 7;
                s1n = __shfl_sync(0xFFFFFFFFu, q[nn],  (tg + 1) & 3, 4);
                s2n = __shfl_sync(0xFFFFFFFFu, q[nn],  (tg + 2) & 3, 4);
                sen = __shfl_sync(0xFFFFFFFFu, ev[nn], (tg + 3) & 3, 4);
                const int jo = 4 * n8 + tg;
                if (jo < TILE_OUT) {
                    const float v1 = (tg < 3) ? s1c : s1n;
                    const float v2 = (tg < 2) ? s2c : s2n;
                    const float e  = (tg < 1) ? sec : sen;
                    const float mx = fmaxf(fmaxf(q[n8], v1), fmaxf(v2, e));
                    const float pos = (mx > rtp) ? rps : -rps;
                    const float neg = (mx > rtm) ? rms : -rms;
                    outp[rr * OUT_PITCH + jo] = (mx >= 0.f) ? pos : neg;
                }
            }
        }

        __syncthreads();   // OUT[ob] + X[xb^1] visible; X[xb]/OUT[ob^1] free

        prev_valid = 1; b_prev = b_cur; t0_prev = t0; nt_prev = nt;
        ob ^= 1; xb ^= 1;
        b = bn; jt = jn;
        g = gn;
    }

    // ---- drain: store the last tile ----
    if (prev_valid && lane < nt_prev) {
        const float* op = OUT + (ob ^ 1) * (COUT * OUT_PITCH);
        #pragma unroll
        for (int it = 0; it < 16; it++) {
            const int row = wid + it * 8;
            out[((size_t)b_prev * COUT + row) * LOUT + t0_prev + lane] =
                op[row * OUT_PITCH + lane];
        }
    }
}

extern "C" void kernel_launch(void* const* d_in, const int* in_sizes, int n_in,
                              void* d_out, int out_size) {
    const float* I  = (const float*)d_in[0];
    const float* W  = (const float*)d_in[1];
    const float* tp = (const float*)d_in[2];
    const float* tm = (const float*)d_in[3];
    const float* ps = (const float*)d_in[4];
    const float* ms = (const float*)d_in[5];
    float* out = (float*)d_out;

    cudaFuncSetAttribute(binconv_kernel,
                         cudaFuncAttributeMaxDynamicSharedMemorySize, SMEM_BYTES);

    pack_A_kernel<<<14, NTHREADS>>>(W);
    binconv_kernel<<<GRID, NTHREADS, SMEM_BYTES>>>(I, tp, tm, ps, ms, out);
}

// round 17
// speedup vs baseline: 1.4296x; 1.0067x over previous
#include <cuda_runtime.h>
#include <cstdint>

// ============================================================================
// Binary conv1d (sign x sign) + maxpool(7,2) + per-channel threshold.
// FP8 e4m3 mma.sync.m16n8k32; A fragments in L1-resident global (g_Apack);
// 3 CTAs/SM. This round: tile geometry N=72 (9 n-blocks) -> TILE_OUT=33,
// cutting total MACs by 1.0% and tile count by 12% (overhead instances).
// ============================================================================

#define BATCH 64
#define CIN 64
#define LEN 16384
#define COUT 128
#define LOUT 8189
#define NBLK 9                  // n-blocks of 8 -> N = 72 conv positions
#define TILE_OUT 33             // pool outputs per tile (uses n 0..70)
#define TILE_P 78               // input rows needed (72 + 6)
#define TILES_PER_B 249         // ceil(8189/33)
#define TOTAL_TILES (BATCH * TILES_PER_B)   // 15936
#define NTHREADS 256
#define GRID 444                             // 3 CTAs per SM

#define X_PITCH 96              // permuted row: LDS.64 conflict-free
#define OUT_PITCH 36
#define N_ITEMS (16 * TILE_P)   // 1248 convert items

// dynamic smem layout
#define SM_OUT  0                                   // float OUT[2][128*36]
#define SM_X    (2 * COUT * OUT_PITCH * 4)          // uchar X[2][78*96]
#define SMEM_BYTES (SM_X + 2 * TILE_P * X_PITCH)    // 51840 B

#define FP8_P1 0x38u

#define MMA_F8(d, a, b0_, b1_)                                                 \
    asm volatile(                                                              \
        "mma.sync.aligned.m16n8k32.row.col.f32.e4m3.e4m3.f32 "                 \
        "{%0,%1,%2,%3},{%4,%5,%6,%7},{%8,%9},{%0,%1,%2,%3};"                   \
        : "+f"((d)[0]), "+f"((d)[1]), "+f"((d)[2]), "+f"((d)[3])               \
        : "r"((a)[0]), "r"((a)[1]), "r"((a)[2]), "r"((a)[3]),                  \
          "r"(b0_), "r"(b1_))

// pre-packed A fragments: [wid][s][lane] -> uint4 (coalesced per warp-step)
__device__ uint4 g_Apack[8 * 14 * 32];

__global__ void pack_A_kernel(const float* __restrict__ W) {
    const int s    = blockIdx.x;           // 0..13
    const int tid  = threadIdx.x;
    const int wid  = tid >> 5;
    const int lane = tid & 31;
    const int gr   = lane >> 2;
    const int tg   = lane & 3;
    uint32_t r[4];
    #pragma unroll
    for (int j = 0; j < 4; j++) {
        const int row = wid * 16 + gr + (j & 1) * 8;
        const int kap = 32 * s + (j >> 1) * 16 + tg * 4;
        uint32_t v = 0;
        #pragma unroll
        for (int i = 0; i < 4; i++) {
            const int kk = kap + i;
            const float w = W[row * 448 + (kk & 63) * 7 + (kk >> 6)];
            v |= (FP8_P1 | ((w < 0.f) ? 0x80u : 0u)) << (8 * i);
        }
        r[j] = v;
    }
    g_Apack[(wid * 14 + s) * 32 + lane] = make_uint4(r[0], r[1], r[2], r[3]);
}

__global__ void __launch_bounds__(NTHREADS, 3)
binconv_kernel(const float* __restrict__ I,
               const float* __restrict__ TP, const float* __restrict__ TMi,
               const float* __restrict__ PS, const float* __restrict__ MS,
               float* __restrict__ out)
{
    extern __shared__ char smem[];
    float*         OUT = (float*)(smem + SM_OUT);        // [2][COUT*OUT_PITCH]
    unsigned char* X   = (unsigned char*)(smem + SM_X);  // [2][TILE_P*X_PITCH]

    const int tid  = threadIdx.x;
    const int lane = tid & 31;
    const int wid  = tid >> 5;
    const int gr   = lane >> 2;
    const int tg   = lane & 3;

    const int r0 = wid * 16 + gr;
    const int r1 = r0 + 8;

    const uint4* __restrict__ Ap = g_Apack + wid * 14 * 32 + lane;

    // ---- prefetch registers: up to 3 items x 4 floats live at once ----
    float pf[3][4];

    auto prefetchA = [&](int b, int P0) {
        const float* Ib = I + (size_t)b * (size_t)CIN * LEN;
        #pragma unroll
        for (int it = 0; it < 3; it++) {
            const int idx = tid + it * NTHREADS;
            const int ci4 = idx / TILE_P;
            const int p   = idx - ci4 * TILE_P;
            const int gl  = P0 - 3 + p;
            const bool inb = (gl >= 0) && (gl < LEN);
            const float* ip = Ib + (size_t)(ci4 * 4) * LEN + gl;
            pf[it][0] = inb ? __ldcs(ip)           : -1.f;
            pf[it][1] = inb ? __ldcs(ip + LEN)     : -1.f;
            pf[it][2] = inb ? __ldcs(ip + 2 * LEN) : -1.f;
            pf[it][3] = inb ? __ldcs(ip + 3 * LEN) : -1.f;
        }
    };
    auto prefetchB = [&](int b, int P0) {
        const float* Ib = I + (size_t)b * (size_t)CIN * LEN;
        #pragma unroll
        for (int it = 0; it < 2; it++) {
            const int idx = tid + (it + 3) * NTHREADS;
            if (idx < N_ITEMS) {
                const int ci4 = idx / TILE_P;
                const int p   = idx - ci4 * TILE_P;
                const int gl  = P0 - 3 + p;
                const bool inb = (gl >= 0) && (gl < LEN);
                const float* ip = Ib + (size_t)(ci4 * 4) * LEN + gl;
                pf[it][0] = inb ? __ldcs(ip)           : -1.f;
                pf[it][1] = inb ? __ldcs(ip + LEN)     : -1.f;
                pf[it][2] = inb ? __ldcs(ip + 2 * LEN) : -1.f;
                pf[it][3] = inb ? __ldcs(ip + 3 * LEN) : -1.f;
            }
        }
    };

    auto cv1 = [&](unsigned char* Xb, int idx, const float* v) {
        const int ci4 = idx / TILE_P;
        const int p   = idx - ci4 * TILE_P;
        const uint32_t u0 = __float_as_uint(v[0]);
        const uint32_t u1 = __float_as_uint(v[1]);
        const uint32_t u2 = __float_as_uint(v[2]);
        const uint32_t u3 = __float_as_uint(v[3]);
        const uint32_t t  = __byte_perm(u0, u1, 0x0073);
        const uint32_t s2 = __byte_perm(u2, u3, 0x7300);
        const uint32_t r  = __byte_perm(t, s2, 0x7610);
        const uint32_t pk = (r & 0x80808080u) | 0x38383838u;
        const int h  = ci4 >> 3;
        const int w  = ci4 & 7;
        const int wp = ((w & 3) << 1) + (w >> 2);
        *(uint32_t*)&Xb[p * X_PITCH + h * 32 + wp * 4] = pk;
    };
    auto convertA = [&](int xb) {
        unsigned char* Xb = X + xb * (TILE_P * X_PITCH);
        #pragma unroll
        for (int it = 0; it < 3; it++) cv1(Xb, tid + it * NTHREADS, pf[it]);
    };
    auto convertB = [&](int xb) {
        unsigned char* Xb = X + xb * (TILE_P * X_PITCH);
        #pragma unroll
        for (int it = 0; it < 2; it++) {
            const int idx = tid + (it + 3) * NTHREADS;
            if (idx < N_ITEMS) cv1(Xb, idx, pf[it]);
        }
    };

    unsigned g = (unsigned)blockIdx.x;
    int b  = (int)(g / TILES_PER_B);
    int jt = (int)g - b * TILES_PER_B;

    int xb = 0, ob = 0;
    int prev_valid = 0, b_prev = 0, t0_prev = 0, nt_prev = 0;

    if (g < TOTAL_TILES) {
        prefetchA(b, jt * (TILE_OUT * 2));
        convertA(0);
        prefetchB(b, jt * (TILE_OUT * 2));
        convertB(0);
    }
    __syncthreads();

    while (g < TOTAL_TILES) {
        const int t0 = jt * TILE_OUT;
        const int nt = min(TILE_OUT, LOUT - t0);
        const int b_cur = b;

        int bn = b, jn = jt + GRID;
        while (jn >= TILES_PER_B) { jn -= TILES_PER_B; bn++; }
        const unsigned gn = g + GRID;
        const int Pn = jn * (TILE_OUT * 2);

        if (gn < TOTAL_TILES) prefetchA(bn, Pn);

        float acc[NBLK][4];
        #pragma unroll
        for (int n8 = 0; n8 < NBLK; n8++)
            #pragma unroll
            for (int r = 0; r < 4; r++) acc[n8][r] = 0.f;

        const unsigned char* Xc = X + xb * (TILE_P * X_PITCH);

        // ---- MMA pairs k = 0..2 (A from L1-resident global) ----
        #pragma unroll
        for (int k = 0; k < 3; k++) {
            const uint4 a0 = Ap[(2 * k) * 32];
            const uint4 a1 = Ap[(2 * k + 1) * 32];
            #pragma unroll
            for (int n8 = 0; n8 < NBLK; n8++) {
                const int prel = n8 * 8 + gr + k;
                const uint2 b0 = *(const uint2*)&Xc[prel * X_PITCH + tg * 8];
                const uint2 b1 = *(const uint2*)&Xc[prel * X_PITCH + 32 + tg * 8];
                MMA_F8(acc[n8], ((const uint32_t*)&a0), b0.x, b0.y);
                MMA_F8(acc[n8], ((const uint32_t*)&a1), b1.x, b1.y);
            }
        }

        // ---- store previous tile's output (tensor shadow) ----
        if (prev_valid) {
            const float* op = OUT + (ob ^ 1) * (COUT * OUT_PITCH);
            const int ntp = nt_prev;
            if (lane < ntp && lane < 32) {
                #pragma unroll
                for (int it = 0; it < 16; it++) {
                    const int row = wid + it * 8;
                    out[((size_t)b_prev * COUT + row) * LOUT + t0_prev + lane] =
                        op[row * OUT_PITCH + lane];
                }
            }
            if (ntp > 32 && lane < 16) {           // column 32 (TILE_OUT=33)
                const int row = wid * 16 + lane;
                out[((size_t)b_prev * COUT + row) * LOUT + t0_prev + 32] =
                    op[row * OUT_PITCH + 32];
            }
        }

        // ---- MMA pairs k = 3..4 ----
        #pragma unroll
        for (int k = 3; k < 5; k++) {
            const uint4 a0 = Ap[(2 * k) * 32];
            const uint4 a1 = Ap[(2 * k + 1) * 32];
            #pragma unroll
            for (int n8 = 0; n8 < NBLK; n8++) {
                const int prel = n8 * 8 + gr + k;
                const uint2 b0 = *(const uint2*)&Xc[prel * X_PITCH + tg * 8];
                const uint2 b1 = *(const uint2*)&Xc[prel * X_PITCH + 32 + tg * 8];
                MMA_F8(acc[n8], ((const uint32_t*)&a0), b0.x, b0.y);
                MMA_F8(acc[n8], ((const uint32_t*)&a1), b1.x, b1.y);
            }
        }

        // ---- convert half A, then issue half B loads (tensor shadow) ----
        if (gn < TOTAL_TILES) { convertA(xb ^ 1); prefetchB(bn, Pn); }

        // ---- MMA pairs k = 5..6 ----
        #pragma unroll
        for (int k = 5; k < 7; k++) {
            const uint4 a0 = Ap[(2 * k) * 32];
            const uint4 a1 = Ap[(2 * k + 1) * 32];
            #pragma unroll
            for (int n8 = 0; n8 < NBLK; n8++) {
                const int prel = n8 * 8 + gr + k;
                const uint2 b0 = *(const uint2*)&Xc[prel * X_PITCH + tg * 8];
                const uint2 b1 = *(const uint2*)&Xc[prel * X_PITCH + 32 + tg * 8];
                MMA_F8(acc[n8], ((const uint32_t*)&a0), b0.x, b0.y);
                MMA_F8(acc[n8], ((const uint32_t*)&a1), b1.x, b1.y);
            }
        }

        if (gn < TOTAL_TILES) convertB(xb ^ 1);

        // ---- pool(7,2) + threshold (rolling shuffles) ----
        #pragma unroll
        for (int row = 0; row < 2; row++) {
            float ev[NBLK], q[NBLK];
            #pragma unroll
            for (int n8 = 0; n8 < NBLK; n8++) {
                ev[n8] = acc[n8][row * 2];
                q[n8]  = fmaxf(acc[n8][row * 2], acc[n8][row * 2 + 1]);
            }
            const int rr = row ? r1 : r0;
            const float rtp = TP[rr], rtm = TMi[rr];
            const float rps = PS[rr], rms = MS[rr];
            float* outp = OUT + ob * (COUT * OUT_PITCH);

            float s1n = __shfl_sync(0xFFFFFFFFu, q[0],  (tg + 1) & 3, 4);
            float s2n = __shfl_sync(0xFFFFFFFFu, q[0],  (tg + 2) & 3, 4);
            float sen = __shfl_sync(0xFFFFFFFFu, ev[0], (tg + 3) & 3, 4);
            #pragma unroll
            for (int n8 = 0; n8 < NBLK; n8++) {
                const float s1c = s1n, s2c = s2n, sec = sen;
                const int nn = (n8 < NBLK - 1) ? n8 + 1 : NBLK - 1;
                s1n = __shfl_sync(0xFFFFFFFFu, q[nn],  (tg + 1) & 3, 4);
                s2n = __shfl_sync(0xFFFFFFFFu, q[nn],  (tg + 2) & 3, 4);
                sen = __shfl_sync(0xFFFFFFFFu, ev[nn], (tg + 3) & 3, 4);
                const int jo = 4 * n8 + tg;
                if (jo < TILE_OUT) {
                    const float v1 = (tg < 3) ? s1c : s1n;
                    const float v2 = (tg < 2) ? s2c : s2n;
                    const float e  = (tg < 1) ? sec : sen;
                    const float mx = fmaxf(fmaxf(q[n8], v1), fmaxf(v2, e));
                    const float pos = (mx > rtp) ? rps : -rps;
                    const float neg = (mx > rtm) ? rms : -rms;
                    outp[rr * OUT_PITCH + jo] = (mx >= 0.f) ? pos : neg;
                }
            }
        }

        __syncthreads();   // OUT[ob] + X[xb^1] visible; X[xb]/OUT[ob^1] free

        prev_valid = 1; b_prev = b_cur; t0_prev = t0; nt_prev = nt;
        ob ^= 1; xb ^= 1;
        b = bn; jt = jn;
        g = gn;
    }

    // ---- drain: store the last tile ----
    if (prev_valid) {
        const float* op = OUT + (ob ^ 1) * (COUT * OUT_PITCH);
        if (lane < nt_prev && lane < 32) {
            #pragma unroll
            for (int it = 0; it < 16; it++) {
                const int row = wid + it * 8;
                out[((size_t)b_prev * COUT + row) * LOUT + t0_prev + lane] =
                    op[row * OUT_PITCH + lane];
            }
        }
        if (nt_prev > 32 && lane < 16) {
            const int row = wid * 16 + lane;
            out[((size_t)b_prev * COUT + row) * LOUT + t0_prev + 32] =
                op[row * OUT_PITCH + 32];
        }
    }
}

extern "C" void kernel_launch(void* const* d_in, const int* in_sizes, int n_in,
                              void* d_out, int out_size) {
    const float* I  = (const float*)d_in[0];
    const float* W  = (const float*)d_in[1];
    const float* tp = (const float*)d_in[2];
    const float* tm = (const float*)d_in[3];
    const float* ps = (const float*)d_in[4];
    const float* ms = (const float*)d_in[5];
    float* out = (float*)d_out;

    cudaFuncSetAttribute(binconv_kernel,
                         cudaFuncAttributeMaxDynamicSharedMemorySize, SMEM_BYTES);

    pack_A_kernel<<<14, NTHREADS>>>(W);
    binconv_kernel<<<GRID, NTHREADS, SMEM_BYTES>>>(I, tp, tm, ps, ms, out);
}